// round 11
// baseline (speedup 1.0000x reference)
#include <cuda_runtime.h>
#include <cuda_fp16.h>
#include <cstdint>

// ============================================================================
// BinaryLinear via 2:4 SPARSE tensor cores: y = x @ sign(W)^T + sign(b)
//  x' fp16 with (x0+x1, x0-x1) pairs; W' 2:4 sparse (one +-1 per pair);
//  mma.sp::ordered_metadata.m16n8k32. Metadata thread mapping:
//   T4i+0 = {lo: row i k0-15,  hi: row i+8 k0-15}
//   T4i+1 = {lo: row i k16-31, hi: row i+8 k16-31}
// R11: single fused convert kernel with streaming (__ldcs) input reads;
// GEMM identical to R10 (at the mma.sp issue floor).
// ============================================================================

#define TOKENS 8192
#define KDIM   4096
#define NDIM   4096

#define BMN 128
#define BNT 128
#define BK  128
#define NKIT (KDIM / BK)            // 32
#define TILES_NF (NDIM / BMN)       // 32
#define TILES_T  (TOKENS / BNT)     // 64

#define A_BYTES   (BMN * 128)                  // 16KB compressed W
#define M_BYTES   2048                         // meta: 8 blk x 4 ks x 64B
#define B_OFF     (A_BYTES + M_BYTES)          // 18432
#define B_BYTES   (BNT * 256)                  // 32KB x'
#define STAGE_BYTES (B_OFF + B_BYTES)          // 51200
#define SMEM_TOTAL  (2 * STAGE_BYTES)          // 102400 -> 2 CTAs/SM

// fused convert kernel dispatch
#define XP_ITEMS  (TOKENS * KDIM / 4)          // 8388608 float4-tasks
#define XP_BLOCKS (XP_ITEMS / 256)             // 32768
#define W_ITEMS   (NDIM * 128)                 // 524288 row-chunk tasks
#define W_BLOCKS  (W_ITEMS / 256)              // 2048
#define CVT_BLOCKS (XP_BLOCKS + W_BLOCKS)      // 34816

__device__ __half   g_xp[(size_t)TOKENS * KDIM];
__device__ __half   g_wc[(size_t)NDIM * (KDIM / 2)];
// meta words: [n/16][ks32(128)][i(8)][khalf(2)] u32
__device__ uint32_t g_meta[(size_t)(NDIM / 16) * 128 * 16];

__device__ __forceinline__ uint32_t smem_u32(const void* p) {
    uint32_t a;
    asm("{ .reg .u64 t; cvta.to.shared.u64 t, %1; cvt.u32.u64 %0, t; }"
        : "=r"(a) : "l"(p));
    return a;
}
__device__ __forceinline__ void cp16(uint32_t saddr, const void* gaddr) {
    asm volatile("cp.async.cg.shared.global [%0], [%1], 16;"
                 :: "r"(saddr), "l"(gaddr));
}
__device__ __forceinline__ void ldsm4(uint32_t* r, uint32_t addr) {
    asm volatile("ldmatrix.sync.aligned.m8n8.x4.shared.b16 {%0,%1,%2,%3}, [%4];"
                 : "=r"(r[0]), "=r"(r[1]), "=r"(r[2]), "=r"(r[3]) : "r"(addr));
}
__device__ __forceinline__ void mma_sp(float* d, const uint32_t* a,
                                       uint32_t b0, uint32_t b1,
                                       uint32_t b2, uint32_t b3, uint32_t e) {
    asm volatile(
        "mma.sp::ordered_metadata.sync.aligned.m16n8k32.row.col.f32.f16.f16.f32 "
        "{%0,%1,%2,%3}, {%4,%5,%6,%7}, {%8,%9,%10,%11}, {%0,%1,%2,%3}, %12, 0x0;"
        : "+f"(d[0]), "+f"(d[1]), "+f"(d[2]), "+f"(d[3])
        : "r"(a[0]), "r"(a[1]), "r"(a[2]), "r"(a[3]),
          "r"(b0), "r"(b1), "r"(b2), "r"(b3), "r"(e));
}

// ---------------- fused pre-pass: x -> x' AND W -> Wc + meta ---------------
__global__ void __launch_bounds__(256) k_cvt_fused(const float4* __restrict__ x,
                                                   const float4* __restrict__ w) {
    if (blockIdx.x < XP_BLOCKS) {
        // x -> (x0+x1, x0-x1) fp16 pairs
        int i = blockIdx.x * 256 + threadIdx.x;
        float4 v = __ldcs(x + i);                      // streaming read
        __half2 h0 = __floats2half2_rn(v.x + v.y, v.x - v.y);
        __half2 h1 = __floats2half2_rn(v.z + v.w, v.z - v.w);
        uint2 o;
        o.x = *reinterpret_cast<uint32_t*>(&h0);
        o.y = *reinterpret_cast<uint32_t*>(&h1);
        reinterpret_cast<uint2*>(g_xp)[i] = o;
    } else {
        // W row-chunk: 32 original k -> 16 compressed +-1 halves + meta word
        int idx = (blockIdx.x - XP_BLOCKS) * 256 + threadIdx.x;
        int n    = idx >> 7;
        int ks32 = idx & 127;
        const float4* src = w + ((size_t)n * KDIM + ks32 * 32) / 4;

        uint32_t meta = 0;
        uint16_t hv[16];
        #pragma unroll
        for (int g = 0; g < 8; g++) {
            float4 v = __ldcs(src + g);                // streaming read
            uint32_t s0 = (__float_as_uint(v.x) >> 31) & 1;
            uint32_t s1 = (__float_as_uint(v.y) >> 31) & 1;
            uint32_t s2 = (__float_as_uint(v.z) >> 31) & 1;
            uint32_t s3 = (__float_as_uint(v.w) >> 31) & 1;
            hv[2 * g]     = (uint16_t)(0x3C00u | (s0 << 15));
            hv[2 * g + 1] = (uint16_t)(0x3C00u | (s2 << 15));
            meta |= ((s0 ^ s1) | ((2u + (s2 ^ s3)) << 2)) << (4 * g);
        }
        uint4* dst = reinterpret_cast<uint4*>(g_wc + (size_t)n * (KDIM / 2) + ks32 * 16);
        dst[0] = *reinterpret_cast<uint4*>(&hv[0]);
        dst[1] = *reinterpret_cast<uint4*>(&hv[8]);

        uint16_t* mp = reinterpret_cast<uint16_t*>(g_meta);
        size_t wbase = (((size_t)(n >> 4) * 128 + ks32) * 16 + (uint32_t)(n & 7) * 2);
        uint32_t half = (n >> 3) & 1;
        mp[(wbase + 0) * 2 + half] = (uint16_t)(meta & 0xFFFF);   // k0-15
        mp[(wbase + 1) * 2 + half] = (uint16_t)(meta >> 16);      // k16-31
    }
}

// ---------------- stage fill ----------------
__device__ __forceinline__ void load_stage(uint32_t sb, int buf,
                                           int n0, int t0, int kt, int tid) {
    uint32_t base = sb + (uint32_t)buf * STAGE_BYTES;
    {   // A (Wc): 128 rows x 128B, swizzle chunk ^ (row&7); 4 cp16/thread
        const int c = tid & 7;
        const int row0 = tid >> 3;      // 0..31
        const __half* g = g_wc + (size_t)(n0 + row0) * (KDIM / 2) + kt * 64 + c * 8;
        uint32_t sw0 = (uint32_t)row0 * 128 + ((uint32_t)((row0 & 7) ^ c) << 4);
        #pragma unroll
        for (int it = 0; it < 4; it++)
            cp16(base + sw0 + (uint32_t)it * 32 * 128,
                 g + (size_t)it * 32 * (KDIM / 2));
    }
    if (tid < 128) {   // meta: 8 blk x 4 ks x 64B
        const int blk = tid >> 4;
        const int ks  = (tid >> 2) & 3;
        const int ch  = tid & 3;
        const uint32_t* g = g_meta
            + (((size_t)(n0 >> 4) + blk) * 128 + (size_t)kt * 4 + ks) * 16 + ch * 4;
        cp16(base + A_BYTES + (uint32_t)(blk * 256 + ks * 64 + ch * 16), g);
    }
    {   // B (x'): 128 rows x 256B, swizzle chunk ^ (row&7); 8 cp16/thread
        const int c = tid & 15;
        const int row0 = tid >> 4;      // 0..15
        const __half* g = g_xp + (size_t)(t0 + row0) * KDIM + kt * BK + c * 8;
        uint32_t sw0 = (uint32_t)row0 * 256 + ((uint32_t)(c ^ (row0 & 7)) << 4);
        #pragma unroll
        for (int it = 0; it < 8; it++)
            cp16(base + B_OFF + sw0 + (uint32_t)it * 16 * 256,
                 g + (size_t)it * 16 * KDIM);
    }
}

// ---------------- sparse GEMM: 8 warps (2 n x 4 t), warp 64x32 --------------
__global__ void __launch_bounds__(256, 2) binlin_gemm(const float* __restrict__ bias,
                                                      float* __restrict__ out) {
    extern __shared__ char smem[];
    const uint32_t sb = smem_u32(smem);
    const int tid = threadIdx.x;
    const int wid = tid >> 5;
    const int lid = tid & 31;

    const int tileNF = blockIdx.x % TILES_NF;   // inner: W reuse within wave
    const int tileT  = blockIdx.x / TILES_NF;
    const int n0 = tileNF * BMN;
    const int t0 = tileT * BNT;

    const int warpM = wid >> 2;               // 0..1  n-slice (64)
    const int warpN = wid & 3;                // 0..3  t-slice (32)

    const int rowa = warpM * 64 + (lid & 15);
    const int ka   = lid >> 4;
    const uint32_t offA0 = (uint32_t)rowa * 128;
    const int ra7 = lid & 7;

    const int rowb_base = warpN * 32 + (lid & 7) + ((lid >> 4) << 3);
    const int kb  = (lid >> 3) & 1;
    const int rb7 = lid & 7;

    const uint32_t moff = (uint32_t)((lid >> 2) * 8 + (lid & 1) * 4);

    float acc[4][4][4];
    #pragma unroll
    for (int i = 0; i < 4; i++)
        #pragma unroll
        for (int j = 0; j < 4; j++)
            #pragma unroll
            for (int r = 0; r < 4; r++) acc[i][j][r] = 0.f;

    load_stage(sb, 0, n0, t0, 0, tid);
    asm volatile("cp.async.commit_group;" ::: "memory");

    int buf_rd = 0, buf_ld = 1;

    for (int kt = 0; kt < NKIT; kt++) {
        asm volatile("cp.async.wait_group 0;" ::: "memory");
        __syncthreads();

        if (kt + 1 < NKIT)
            load_stage(sb, buf_ld, n0, t0, kt + 1, tid);
        asm volatile("cp.async.commit_group;" ::: "memory");
        buf_ld ^= 1;

        const uint32_t bufA = sb + (uint32_t)buf_rd * STAGE_BYTES;
        const uint32_t bufM = bufA + A_BYTES;
        const uint32_t bufB = bufA + B_OFF;
        buf_rd ^= 1;

        #pragma unroll
        for (int ks = 0; ks < 4; ks++) {      // four k32 steps per kt
            uint32_t P[2][2][4];
            #pragma unroll
            for (int u = 0; u < 2; u++)
                #pragma unroll
                for (int h = 0; h < 2; h++) {
                    int ks2 = ks * 2 + h;
                    uint32_t bd = bufB + (uint32_t)(rowb_base + 16 * u) * 256
                                + ((uint32_t)((ks2 * 2 + kb) ^ rb7) << 4);
                    ldsm4(P[u][h], bd);
                }
            #pragma unroll
            for (int mi = 0; mi < 4; mi++) {
                uint32_t a_r[4];
                ldsm4(a_r, bufA + offA0 + (uint32_t)(mi * 16 * 128)
                           + ((uint32_t)((ks * 2 + ka) ^ ra7) << 4));
                uint32_t e;
                asm volatile("ld.shared.b32 %0, [%1];" : "=r"(e)
                    : "r"(bufM + (uint32_t)((warpM * 4 + mi) * 256 + ks * 64) + moff));
                #pragma unroll
                for (int tg = 0; tg < 4; tg++) {
                    const int u = tg >> 1;
                    const int eo = (tg & 1) * 2;
                    mma_sp(acc[mi][tg], a_r,
                           P[u][0][eo], P[u][0][eo + 1],
                           P[u][1][eo], P[u][1][eo + 1], e);
                }
            }
        }
    }

    // ---------------- epilogue: y[t][n] = acc + sign(bias[n]) ----------------
    const int n0w = n0 + warpM * 64;
    const int t0w = t0 + warpN * 32;
    const int qr = lid >> 2;
    const int qc = (lid & 3) * 2;

    float sbv[4][2];
    #pragma unroll
    for (int mi = 0; mi < 4; mi++) {
        sbv[mi][0] = bias[n0w + mi * 16 + qr]     >= 0.f ? 1.f : -1.f;
        sbv[mi][1] = bias[n0w + mi * 16 + qr + 8] >= 0.f ? 1.f : -1.f;
    }

    #pragma unroll
    for (int mi = 0; mi < 4; mi++) {
        const int nlo = n0w + mi * 16 + qr;
        #pragma unroll
        for (int tg = 0; tg < 4; tg++) {
            const int t = t0w + tg * 8 + qc;
            out[(size_t)t * NDIM + nlo]           = acc[mi][tg][0] + sbv[mi][0];
            out[(size_t)(t + 1) * NDIM + nlo]     = acc[mi][tg][1] + sbv[mi][0];
            out[(size_t)t * NDIM + nlo + 8]       = acc[mi][tg][2] + sbv[mi][1];
            out[(size_t)(t + 1) * NDIM + nlo + 8] = acc[mi][tg][3] + sbv[mi][1];
        }
    }
}

// ---------------- entry ----------------
extern "C" void kernel_launch(void* const* d_in, const int* in_sizes, int n_in,
                              void* d_out, int out_size) {
    const float* x    = (const float*)d_in[0];
    const float* w    = (const float*)d_in[1];
    const float* bias = (const float*)d_in[2];
    float* out = (float*)d_out;
    (void)in_sizes; (void)n_in; (void)out_size;

    k_cvt_fused<<<CVT_BLOCKS, 256>>>((const float4*)x, (const float4*)w);

    cudaFuncSetAttribute(binlin_gemm,
                         cudaFuncAttributeMaxDynamicSharedMemorySize, SMEM_TOTAL);
    binlin_gemm<<<TILES_NF * TILES_T, 256, SMEM_TOTAL>>>(bias, out);
}

// round 13
// speedup vs baseline: 1.0369x; 1.0369x over previous
#include <cuda_runtime.h>
#include <cuda_fp16.h>
#include <cstdint>

// ============================================================================
// BinaryLinear via 2:4 SPARSE tensor cores: y = x @ sign(W)^T + sign(b)
//  x' fp16 with (x0+x1, x0-x1) pairs; W' 2:4 sparse (one +-1 per pair);
//  mma.sp::ordered_metadata.m16n8k32. Metadata thread mapping:
//   T4i+0 = {lo: row i k0-15,  hi: row i+8 k0-15}
//   T4i+1 = {lo: row i k16-31, hi: row i+8 k16-31}
// R12: manual software pipelining in the mainloop (volatile asm blocks ptxas
// reordering): A-frag+meta double-buffered across mi, B-frags double-buffered
// across ks. Everything else identical to R11.
// ============================================================================

#define TOKENS 8192
#define KDIM   4096
#define NDIM   4096

#define BMN 128
#define BNT 128
#define BK  128
#define NKIT (KDIM / BK)            // 32
#define TILES_NF (NDIM / BMN)       // 32
#define TILES_T  (TOKENS / BNT)     // 64

#define A_BYTES   (BMN * 128)                  // 16KB compressed W
#define M_BYTES   2048                         // meta: 8 blk x 4 ks x 64B
#define B_OFF     (A_BYTES + M_BYTES)          // 18432
#define B_BYTES   (BNT * 256)                  // 32KB x'
#define STAGE_BYTES (B_OFF + B_BYTES)          // 51200
#define SMEM_TOTAL  (2 * STAGE_BYTES)          // 102400 -> 2 CTAs/SM

// fused convert kernel dispatch
#define XP_ITEMS  (TOKENS * KDIM / 4)
#define XP_BLOCKS (XP_ITEMS / 256)             // 32768
#define W_ITEMS   (NDIM * 128)
#define W_BLOCKS  (W_ITEMS / 256)              // 2048
#define CVT_BLOCKS (XP_BLOCKS + W_BLOCKS)      // 34816

__device__ __half   g_xp[(size_t)TOKENS * KDIM];
__device__ __half   g_wc[(size_t)NDIM * (KDIM / 2)];
__device__ uint32_t g_meta[(size_t)(NDIM / 16) * 128 * 16];

__device__ __forceinline__ uint32_t smem_u32(const void* p) {
    uint32_t a;
    asm("{ .reg .u64 t; cvta.to.shared.u64 t, %1; cvt.u32.u64 %0, t; }"
        : "=r"(a) : "l"(p));
    return a;
}
__device__ __forceinline__ void cp16(uint32_t saddr, const void* gaddr) {
    asm volatile("cp.async.cg.shared.global [%0], [%1], 16;"
                 :: "r"(saddr), "l"(gaddr));
}
__device__ __forceinline__ void ldsm4(uint32_t* r, uint32_t addr) {
    asm volatile("ldmatrix.sync.aligned.m8n8.x4.shared.b16 {%0,%1,%2,%3}, [%4];"
                 : "=r"(r[0]), "=r"(r[1]), "=r"(r[2]), "=r"(r[3]) : "r"(addr));
}
__device__ __forceinline__ void mma_sp(float* d, const uint32_t* a,
                                       uint32_t b0, uint32_t b1,
                                       uint32_t b2, uint32_t b3, uint32_t e) {
    asm volatile(
        "mma.sp::ordered_metadata.sync.aligned.m16n8k32.row.col.f32.f16.f16.f32 "
        "{%0,%1,%2,%3}, {%4,%5,%6,%7}, {%8,%9,%10,%11}, {%0,%1,%2,%3}, %12, 0x0;"
        : "+f"(d[0]), "+f"(d[1]), "+f"(d[2]), "+f"(d[3])
        : "r"(a[0]), "r"(a[1]), "r"(a[2]), "r"(a[3]),
          "r"(b0), "r"(b1), "r"(b2), "r"(b3), "r"(e));
}

// ---------------- fused pre-pass: x -> x' AND W -> Wc + meta ---------------
__global__ void __launch_bounds__(256) k_cvt_fused(const float4* __restrict__ x,
                                                   const float4* __restrict__ w) {
    if (blockIdx.x < XP_BLOCKS) {
        int i = blockIdx.x * 256 + threadIdx.x;
        float4 v = __ldcs(x + i);
        __half2 h0 = __floats2half2_rn(v.x + v.y, v.x - v.y);
        __half2 h1 = __floats2half2_rn(v.z + v.w, v.z - v.w);
        uint2 o;
        o.x = *reinterpret_cast<uint32_t*>(&h0);
        o.y = *reinterpret_cast<uint32_t*>(&h1);
        reinterpret_cast<uint2*>(g_xp)[i] = o;
    } else {
        int idx = (blockIdx.x - XP_BLOCKS) * 256 + threadIdx.x;
        int n    = idx >> 7;
        int ks32 = idx & 127;
        const float4* src = w + ((size_t)n * KDIM + ks32 * 32) / 4;

        uint32_t meta = 0;
        uint16_t hv[16];
        #pragma unroll
        for (int g = 0; g < 8; g++) {
            float4 v = __ldcs(src + g);
            uint32_t s0 = (__float_as_uint(v.x) >> 31) & 1;
            uint32_t s1 = (__float_as_uint(v.y) >> 31) & 1;
            uint32_t s2 = (__float_as_uint(v.z) >> 31) & 1;
            uint32_t s3 = (__float_as_uint(v.w) >> 31) & 1;
            hv[2 * g]     = (uint16_t)(0x3C00u | (s0 << 15));
            hv[2 * g + 1] = (uint16_t)(0x3C00u | (s2 << 15));
            meta |= ((s0 ^ s1) | ((2u + (s2 ^ s3)) << 2)) << (4 * g);
        }
        uint4* dst = reinterpret_cast<uint4*>(g_wc + (size_t)n * (KDIM / 2) + ks32 * 16);
        dst[0] = *reinterpret_cast<uint4*>(&hv[0]);
        dst[1] = *reinterpret_cast<uint4*>(&hv[8]);

        uint16_t* mp = reinterpret_cast<uint16_t*>(g_meta);
        size_t wbase = (((size_t)(n >> 4) * 128 + ks32) * 16 + (uint32_t)(n & 7) * 2);
        uint32_t half = (n >> 3) & 1;
        mp[(wbase + 0) * 2 + half] = (uint16_t)(meta & 0xFFFF);
        mp[(wbase + 1) * 2 + half] = (uint16_t)(meta >> 16);
    }
}

// ---------------- stage fill ----------------
__device__ __forceinline__ void load_stage(uint32_t sb, int buf,
                                           int n0, int t0, int kt, int tid) {
    uint32_t base = sb + (uint32_t)buf * STAGE_BYTES;
    {   // A (Wc): 128 rows x 128B, swizzle chunk ^ (row&7); 4 cp16/thread
        const int c = tid & 7;
        const int row0 = tid >> 3;
        const __half* g = g_wc + (size_t)(n0 + row0) * (KDIM / 2) + kt * 64 + c * 8;
        uint32_t sw0 = (uint32_t)row0 * 128 + ((uint32_t)((row0 & 7) ^ c) << 4);
        #pragma unroll
        for (int it = 0; it < 4; it++)
            cp16(base + sw0 + (uint32_t)it * 32 * 128,
                 g + (size_t)it * 32 * (KDIM / 2));
    }
    if (tid < 128) {   // meta
        const int blk = tid >> 4;
        const int ks  = (tid >> 2) & 3;
        const int ch  = tid & 3;
        const uint32_t* g = g_meta
            + (((size_t)(n0 >> 4) + blk) * 128 + (size_t)kt * 4 + ks) * 16 + ch * 4;
        cp16(base + A_BYTES + (uint32_t)(blk * 256 + ks * 64 + ch * 16), g);
    }
    {   // B (x'): 128 rows x 256B, swizzle chunk ^ (row&7); 8 cp16/thread
        const int c = tid & 15;
        const int row0 = tid >> 4;
        const __half* g = g_xp + (size_t)(t0 + row0) * KDIM + kt * BK + c * 8;
        uint32_t sw0 = (uint32_t)row0 * 256 + ((uint32_t)(c ^ (row0 & 7)) << 4);
        #pragma unroll
        for (int it = 0; it < 8; it++)
            cp16(base + B_OFF + sw0 + (uint32_t)it * 16 * 256,
                 g + (size_t)it * 16 * KDIM);
    }
}

// ---------------- sparse GEMM: 8 warps (2 n x 4 t), warp 64x32 --------------
__global__ void __launch_bounds__(256, 2) binlin_gemm(const float* __restrict__ bias,
                                                      float* __restrict__ out) {
    extern __shared__ char smem[];
    const uint32_t sb = smem_u32(smem);
    const int tid = threadIdx.x;
    const int wid = tid >> 5;
    const int lid = tid & 31;

    const int tileNF = blockIdx.x % TILES_NF;
    const int tileT  = blockIdx.x / TILES_NF;
    const int n0 = tileNF * BMN;
    const int t0 = tileT * BNT;

    const int warpM = wid >> 2;
    const int warpN = wid & 3;

    const int rowa = warpM * 64 + (lid & 15);
    const int ka   = lid >> 4;
    const uint32_t offA0 = (uint32_t)rowa * 128;
    const int ra7 = lid & 7;

    const int rowb_base = warpN * 32 + (lid & 7) + ((lid >> 4) << 3);
    const int kb  = (lid >> 3) & 1;
    const int rb7 = lid & 7;

    const uint32_t moff = (uint32_t)((lid >> 2) * 8 + (lid & 1) * 4)
                        + (uint32_t)(warpM * 4) * 256;

    float acc[4][4][4];
    #pragma unroll
    for (int i = 0; i < 4; i++)
        #pragma unroll
        for (int j = 0; j < 4; j++)
            #pragma unroll
            for (int r = 0; r < 4; r++) acc[i][j][r] = 0.f;

    load_stage(sb, 0, n0, t0, 0, tid);
    asm volatile("cp.async.commit_group;" ::: "memory");

    int buf_rd = 0, buf_ld = 1;

    for (int kt = 0; kt < NKIT; kt++) {
        asm volatile("cp.async.wait_group 0;" ::: "memory");
        __syncthreads();

        if (kt + 1 < NKIT)
            load_stage(sb, buf_ld, n0, t0, kt + 1, tid);
        asm volatile("cp.async.commit_group;" ::: "memory");
        buf_ld ^= 1;

        const uint32_t bufA = sb + (uint32_t)buf_rd * STAGE_BYTES;
        const uint32_t bufM = bufA + A_BYTES;
        const uint32_t bufB = bufA + B_OFF;
        buf_rd ^= 1;

        // ---- software-pipelined mainloop ----
        // P: B-fragments, double-buffered across ks.
        // a/e: A-fragment + metadata, double-buffered across mi.
        uint32_t P[2][2][2][4];     // [ksbuf][u][h][4]
        uint32_t a[2][4];
        uint32_t em[2];

        // prime P for ks=0 (buffer 0)
        #pragma unroll
        for (int u = 0; u < 2; u++)
            #pragma unroll
            for (int h = 0; h < 2; h++)
                ldsm4(P[0][u][h], bufB + (uint32_t)(rowb_base + 16 * u) * 256
                        + ((uint32_t)((h * 2 + kb) ^ rb7) << 4));

        #pragma unroll
        for (int ks = 0; ks < 4; ks++) {
            const int pb = ks & 1;
            // prime a/e for mi=0
            ldsm4(a[0], bufA + offA0
                        + ((uint32_t)((ks * 2 + ka) ^ ra7) << 4));
            asm volatile("ld.shared.b32 %0, [%1];" : "=r"(em[0])
                : "r"(bufM + moff + (uint32_t)(ks * 64)));

            #pragma unroll
            for (int mi = 0; mi < 4; mi++) {
                const int cur = mi & 1;
                if (mi < 3) {
                    // prefetch next mi's A-frag + meta
                    ldsm4(a[cur ^ 1], bufA + offA0 + (uint32_t)((mi + 1) * 16 * 128)
                                + ((uint32_t)((ks * 2 + ka) ^ ra7) << 4));
                    asm volatile("ld.shared.b32 %0, [%1];" : "=r"(em[cur ^ 1])
                        : "r"(bufM + moff + (uint32_t)((mi + 1) * 256 + ks * 64)));
                } else if (ks < 3) {
                    // prefetch next ks's B-frags into the alternate buffer
                    #pragma unroll
                    for (int u = 0; u < 2; u++)
                        #pragma unroll
                        for (int h = 0; h < 2; h++)
                            ldsm4(P[pb ^ 1][u][h],
                                  bufB + (uint32_t)(rowb_base + 16 * u) * 256
                                  + ((uint32_t)(((ks + 1) * 4 + h * 2 + kb) ^ rb7) << 4));
                }
                #pragma unroll
                for (int tg = 0; tg < 4; tg++) {
                    const int u = tg >> 1;
                    const int eo = (tg & 1) * 2;
                    mma_sp(acc[mi][tg], a[cur],
                           P[pb][u][0][eo], P[pb][u][0][eo + 1],
                           P[pb][u][1][eo], P[pb][u][1][eo + 1], em[cur]);
                }
            }
        }
    }

    // ---------------- epilogue: y[t][n] = acc + sign(bias[n]) ----------------
    const int n0w = n0 + warpM * 64;
    const int t0w = t0 + warpN * 32;
    const int qr = lid >> 2;
    const int qc = (lid & 3) * 2;

    float sbv[4][2];
    #pragma unroll
    for (int mi = 0; mi < 4; mi++) {
        sbv[mi][0] = bias[n0w + mi * 16 + qr]     >= 0.f ? 1.f : -1.f;
        sbv[mi][1] = bias[n0w + mi * 16 + qr + 8] >= 0.f ? 1.f : -1.f;
    }

    #pragma unroll
    for (int mi = 0; mi < 4; mi++) {
        const int nlo = n0w + mi * 16 + qr;
        #pragma unroll
        for (int tg = 0; tg < 4; tg++) {
            const int t = t0w + tg * 8 + qc;
            out[(size_t)t * NDIM + nlo]           = acc[mi][tg][0] + sbv[mi][0];
            out[(size_t)(t + 1) * NDIM + nlo]     = acc[mi][tg][1] + sbv[mi][0];
            out[(size_t)t * NDIM + nlo + 8]       = acc[mi][tg][2] + sbv[mi][1];
            out[(size_t)(t + 1) * NDIM + nlo + 8] = acc[mi][tg][3] + sbv[mi][1];
        }
    }
}

// ---------------- entry ----------------
extern "C" void kernel_launch(void* const* d_in, const int* in_sizes, int n_in,
                              void* d_out, int out_size) {
    const float* x    = (const float*)d_in[0];
    const float* w    = (const float*)d_in[1];
    const float* bias = (const float*)d_in[2];
    float* out = (float*)d_out;
    (void)in_sizes; (void)n_in; (void)out_size;

    k_cvt_fused<<<CVT_BLOCKS, 256>>>((const float4*)x, (const float4*)w);

    cudaFuncSetAttribute(binlin_gemm,
                         cudaFuncAttributeMaxDynamicSharedMemorySize, SMEM_TOTAL);
    binlin_gemm<<<TILES_NF * TILES_T, 256, SMEM_TOTAL>>>(bias, out);
}